// round 11
// baseline (speedup 1.0000x reference)
#include <cuda_runtime.h>
#include <cuda_bf16.h>
#include <cstdint>
#include <math.h>

#define TOK 1024
#define NE 8
#define HD 1024
#define ID 768
#define NPAIR (2*TOK)

#define CHUNK 32             // K elems per stage chunk (128B rows)
#define STGSZ 32768          // 256 rows * 128B per stage
#define NSTG  4

// ------------------------- device scratch (static, no allocs) -------------
__device__ int   g_cnt[NE];
__device__ int   g_bucket[NE][TOK];
__device__ float g_wt[NPAIR];

__device__ float xs[(size_t)TOK*HD];               // tf32-rounded x
__device__ float w13q[(size_t)NE*2*ID*HD];         // tf32-rounded dequant w13
__device__ float w2q[(size_t)NE*HD*ID];            // tf32-rounded dequant w2
__device__ float g_act[(size_t)NPAIR*ID];          // tf32-rounded activations
__device__ float g_os[(size_t)NPAIR*HD];           // per-slot outputs

// ------------------------- PTX helpers (baseline ISA only) ----------------
__device__ __forceinline__ uint32_t smem_u32(const void* p) {
    uint32_t a;
    asm("{ .reg .u64 t; cvta.to.shared.u64 t, %1; cvt.u32.u64 %0, t; }" : "=r"(a) : "l"(p));
    return a;
}
__device__ __forceinline__ void cp16(uint32_t dst, const void* src) {
    asm volatile("cp.async.cg.shared.global [%0], [%1], 16;" :: "r"(dst), "l"(src));
}
__device__ __forceinline__ void cp_commit() {
    asm volatile("cp.async.commit_group;");
}
__device__ __forceinline__ void ldsm4(uint32_t* r, uint32_t addr) {
    asm volatile("ldmatrix.sync.aligned.m8n8.x4.shared.b16 {%0,%1,%2,%3}, [%4];"
        : "=r"(r[0]), "=r"(r[1]), "=r"(r[2]), "=r"(r[3]) : "r"(addr));
}
__device__ __forceinline__ void mma_tf32(float* d, const uint32_t* a, uint32_t b0, uint32_t b1) {
    asm volatile("mma.sync.aligned.m16n8k8.row.col.f32.tf32.tf32.f32 "
        "{%0,%1,%2,%3}, {%4,%5,%6,%7}, {%8,%9}, {%0,%1,%2,%3};"
        : "+f"(d[0]), "+f"(d[1]), "+f"(d[2]), "+f"(d[3])
        : "r"(a[0]), "r"(a[1]), "r"(a[2]), "r"(a[3]), "r"(b0), "r"(b1));
}
__device__ __forceinline__ uint32_t to_tf32(float f) {
    uint32_t r;
    asm("cvt.rna.tf32.f32 %0, %1;" : "=r"(r) : "f"(f));
    return r;
}

// ------------------------- routing ---------------------------------------
__global__ void routing_kernel(const float* __restrict__ rl) {
    int t = threadIdx.x;
    if (t < NE) g_cnt[t] = 0;
    __syncthreads();
    float l[NE];
#pragma unroll
    for (int e = 0; e < NE; e++) l[e] = rl[t * NE + e];
    int i0 = 0; float v0 = l[0];
#pragma unroll
    for (int e = 1; e < NE; e++) if (l[e] > v0) { v0 = l[e]; i0 = e; }
    int i1 = -1; float v1 = -3.4e38f;
#pragma unroll
    for (int e = 0; e < NE; e++) if (e != i0 && l[e] > v1) { v1 = l[e]; i1 = e; }
    float e1 = expf(v1 - v0);
    float inv = 1.0f / (1.0f + e1);
    int p0 = 2 * t, p1 = 2 * t + 1;
    g_wt[p0] = inv;
    g_wt[p1] = e1 * inv;
    int pos0 = atomicAdd(&g_cnt[i0], 1); g_bucket[i0][pos0] = p0;
    int pos1 = atomicAdd(&g_cnt[i1], 1); g_bucket[i1][pos1] = p1;
}

// ------------------------- prepass converts (tf32 round + dequant) --------
__global__ void convert_x_kernel(const float* __restrict__ x) {
    size_t i16 = ((size_t)blockIdx.x * 256 + threadIdx.x) * 16;
#pragma unroll
    for (int q = 0; q < 4; q++) {
        float4 v = *(const float4*)(x + i16 + q * 4);
        float4 o;
        o.x = __uint_as_float(to_tf32(v.x));
        o.y = __uint_as_float(to_tf32(v.y));
        o.z = __uint_as_float(to_tf32(v.z));
        o.w = __uint_as_float(to_tf32(v.w));
        *(float4*)(xs + i16 + q * 4) = o;
    }
}

__global__ void convert_w13_kernel(const float* __restrict__ w, const float* __restrict__ ws) {
    size_t i16 = ((size_t)blockIdx.x * 256 + threadIdx.x) * 16;
    size_t row = i16 >> 10;
    int h0 = (int)(i16 & 1023);
    float s = ws[row * (HD / 128) + (h0 >> 7)];
#pragma unroll
    for (int q = 0; q < 4; q++) {
        float4 v = *(const float4*)(w + i16 + q * 4);
        float4 o;
        o.x = __uint_as_float(to_tf32(v.x * s));
        o.y = __uint_as_float(to_tf32(v.y * s));
        o.z = __uint_as_float(to_tf32(v.z * s));
        o.w = __uint_as_float(to_tf32(v.w * s));
        *(float4*)(w13q + i16 + q * 4) = o;
    }
}

__global__ void convert_w2_kernel(const float* __restrict__ w, const float* __restrict__ ws) {
    size_t i16 = ((size_t)blockIdx.x * 256 + threadIdx.x) * 16;
    size_t row = i16 / ID;
    int c0 = (int)(i16 - row * ID);
    float s = ws[row * (ID / 128) + (c0 >> 7)];
#pragma unroll
    for (int q = 0; q < 4; q++) {
        float4 v = *(const float4*)(w + i16 + q * 4);
        float4 o;
        o.x = __uint_as_float(to_tf32(v.x * s));
        o.y = __uint_as_float(to_tf32(v.y * s));
        o.z = __uint_as_float(to_tf32(v.z * s));
        o.w = __uint_as_float(to_tf32(v.w * s));
        *(float4*)(w2q + i16 + q * 4) = o;
    }
}

// ===========================================================================
// GEMM geometry: block tile 128(m) x 128(n), K-chunk 32 fp32 (128B rows).
// Stage = [A 128 rows | B 128 rows] = 32KB; 4 stages, pure cp.async pipeline
// with uniform wait_group 3 (empty commit groups keep the count at tail).
// Swizzle: off = row*128 + ((piece*16) ^ ((row&7)<<4)).
// 8 warps: mw=wid>>2 (2 x 64 m-rows), nw=wid&3 (4 x 32 n-cols).
// ===========================================================================

// ------------------------- GEMM1 (x @ w13^T, fused silu*up) ---------------
__global__ __launch_bounds__(256, 1) void gemm1_kernel(const float* __restrict__ w13qp)
{
    int e  = blockIdx.z;
    int Me = g_cnt[e];
    int m0 = blockIdx.y * 128;
    if (m0 >= Me) return;
    int n0g = blockIdx.x * 64;

    extern __shared__ __align__(16) char dynraw[];
    __shared__ int s_tok[128];
    __shared__ int s_pair[128];

    int tid = threadIdx.x, wid = tid >> 5, lane = tid & 31;
    uint32_t dynb0 = smem_u32(dynraw);
    uint32_t dynb = (dynb0 + 1023u) & ~1023u;
    float* s_up = (float*)(dynraw + (dynb - dynb0));   // reused after mainloop

    if (tid < 128) {
        int r = m0 + tid;
        int pr = (r < Me) ? g_bucket[e][r] : 0;
        s_pair[tid] = (r < Me) ? pr : -1;
        s_tok[tid]  = pr >> 1;
    }
    __syncthreads();

    // fill maps: 8 tasks/thread, task = tid + it*256 -> row = task>>3, piece = task&7
    const float* gsrc[8];
    uint32_t sdst[8];
#pragma unroll
    for (int it = 0; it < 8; it++) {
        int task = tid + it * 256;
        int row = task >> 3, piece = task & 7;
        const float* p;
        if (row < 128) {
            p = xs + (size_t)s_tok[row] * HD;
        } else {
            int r = row - 128;
            int brow = (r < 64) ? (n0g + r) : (ID + n0g + (r - 64));
            p = w13qp + ((size_t)e * 2 * ID + brow) * HD;
        }
        gsrc[it] = p + piece * 4;
        sdst[it] = dynb + row * 128 + ((piece * 16) ^ ((row & 7) << 4));
    }

    const int NC = HD / CHUNK;   // 32
    // prologue: chunks 0..2 -> stages 0..2
#pragma unroll
    for (int pc = 0; pc < 3; pc++) {
#pragma unroll
        for (int it = 0; it < 8; it++) cp16(sdst[it] + pc * STGSZ, gsrc[it] + pc * CHUNK);
        cp_commit();
    }

    float acc[4][4][4] = {};
    int mw = wid >> 2, nw = wid & 3;
    uint32_t sw    = (lane & 7) << 4;
    uint32_t aBase = dynb + (uint32_t)(mw * 64 + ((lane >> 3) & 1) * 8 + (lane & 7)) * 128;
    uint32_t aK    = (lane >> 4) * 16;
    uint32_t bBase = dynb + 16384 + (uint32_t)(nw * 32 + (lane >> 4) * 8 + (lane & 7)) * 128;
    uint32_t bK    = ((lane >> 3) & 1) * 16;

    for (int c = 0; c < NC; c++) {
        int st = c & 3;
        if (c + 3 < NC) {
            uint32_t so = (uint32_t)((c + 3) & 3) * STGSZ;
            uint32_t ko = (uint32_t)(c + 3) * CHUNK;
#pragma unroll
            for (int it = 0; it < 8; it++) cp16(sdst[it] + so, gsrc[it] + ko);
        }
        cp_commit();                             // empty group at tail keeps count
        asm volatile("cp.async.wait_group 3;");
        __syncthreads();

        uint32_t ab = aBase + st * STGSZ, bb = bBase + st * STGSZ;
#pragma unroll
        for (int ks = 0; ks < 4; ks++) {
            uint32_t A[4][4], B[2][4];
#pragma unroll
            for (int mt = 0; mt < 4; mt++)
                ldsm4(A[mt], ab + mt * 2048 + ((aK + ks * 32) ^ sw));
#pragma unroll
            for (int p = 0; p < 2; p++)
                ldsm4(B[p], bb + p * 2048 + ((bK + ks * 32) ^ sw));
#pragma unroll
            for (int mt = 0; mt < 4; mt++)
#pragma unroll
                for (int nt = 0; nt < 4; nt++)
                    mma_tf32(acc[mt][nt], A[mt], B[nt >> 1][(nt & 1) * 2], B[nt >> 1][(nt & 1) * 2 + 1]);
        }
        __syncthreads();
    }

    // ---- epilogue: up warps (nw>=2) stash to smem, gate warps fuse silu ----
    int g = lane >> 2, t2 = (lane & 3) * 2;
    if (nw >= 2) {
#pragma unroll
        for (int mt = 0; mt < 4; mt++)
#pragma unroll
            for (int nt = 0; nt < 4; nt++) {
                int j = (nw - 2) * 32 + nt * 8 + t2;
                int r = mw * 64 + mt * 16 + g;
                *(float2*)&s_up[r * 66 + j]       = make_float2(acc[mt][nt][0], acc[mt][nt][1]);
                *(float2*)&s_up[(r + 8) * 66 + j] = make_float2(acc[mt][nt][2], acc[mt][nt][3]);
            }
    }
    __syncthreads();
    if (nw < 2) {
#pragma unroll
        for (int mt = 0; mt < 4; mt++)
#pragma unroll
            for (int nt = 0; nt < 4; nt++) {
                int j = nw * 32 + nt * 8 + t2;
                int r0 = mw * 64 + mt * 16 + g, r1 = r0 + 8;
                float2 u0 = *(float2*)&s_up[r0 * 66 + j];
                float2 u1 = *(float2*)&s_up[r1 * 66 + j];
                float g00 = acc[mt][nt][0], g01 = acc[mt][nt][1];
                float g10 = acc[mt][nt][2], g11 = acc[mt][nt][3];
                float a00 = u0.x * (g00 / (1.0f + __expf(-g00)));
                float a01 = u0.y * (g01 / (1.0f + __expf(-g01)));
                float a10 = u1.x * (g10 / (1.0f + __expf(-g10)));
                float a11 = u1.y * (g11 / (1.0f + __expf(-g11)));
                int p0 = s_pair[r0], p1 = s_pair[r1];
                if (p0 >= 0) {
                    *(float2*)(g_act + (size_t)p0 * ID + n0g + j) = make_float2(
                        __uint_as_float(to_tf32(a00)), __uint_as_float(to_tf32(a01)));
                }
                if (p1 >= 0) {
                    *(float2*)(g_act + (size_t)p1 * ID + n0g + j) = make_float2(
                        __uint_as_float(to_tf32(a10)), __uint_as_float(to_tf32(a11)));
                }
            }
    }
}

// ------------------------- GEMM2 (act @ w2^T, weighted) -------------------
__global__ __launch_bounds__(256, 1) void gemm2_kernel(const float* __restrict__ w2qp)
{
    int e  = blockIdx.z;
    int Me = g_cnt[e];
    int m0 = blockIdx.y * 128;
    if (m0 >= Me) return;
    int n0 = blockIdx.x * 128;

    extern __shared__ __align__(16) char dynraw[];
    __shared__ int s_arow[128];
    __shared__ int s_pair[128];

    int tid = threadIdx.x, wid = tid >> 5, lane = tid & 31;
    uint32_t dynb0 = smem_u32(dynraw);
    uint32_t dynb = (dynb0 + 1023u) & ~1023u;

    if (tid < 128) {
        int r = m0 + tid;
        int pr = (r < Me) ? g_bucket[e][r] : 0;
        s_pair[tid] = (r < Me) ? pr : -1;
        s_arow[tid] = pr;
    }
    __syncthreads();

    const float* gsrc[8];
    uint32_t sdst[8];
#pragma unroll
    for (int it = 0; it < 8; it++) {
        int task = tid + it * 256;
        int row = task >> 3, piece = task & 7;
        const float* p;
        if (row < 128) p = g_act + (size_t)s_arow[row] * ID;
        else           p = w2qp + ((size_t)e * HD + n0 + (row - 128)) * ID;
        gsrc[it] = p + piece * 4;
        sdst[it] = dynb + row * 128 + ((piece * 16) ^ ((row & 7) << 4));
    }

    const int NC = ID / CHUNK;   // 24
#pragma unroll
    for (int pc = 0; pc < 3; pc++) {
#pragma unroll
        for (int it = 0; it < 8; it++) cp16(sdst[it] + pc * STGSZ, gsrc[it] + pc * CHUNK);
        cp_commit();
    }

    float acc[4][4][4] = {};
    int mw = wid >> 2, nw = wid & 3;
    uint32_t sw    = (lane & 7) << 4;
    uint32_t aBase = dynb + (uint32_t)(mw * 64 + ((lane >> 3) & 1) * 8 + (lane & 7)) * 128;
    uint32_t aK    = (lane >> 4) * 16;
    uint32_t bBase = dynb + 16384 + (uint32_t)(nw * 32 + (lane >> 4) * 8 + (lane & 7)) * 128;
    uint32_t bK    = ((lane >> 3) & 1) * 16;

    for (int c = 0; c < NC; c++) {
        int st = c & 3;
        if (c + 3 < NC) {
            uint32_t so = (uint32_t)((c + 3) & 3) * STGSZ;
            uint32_t ko = (uint32_t)(c + 3) * CHUNK;
#pragma unroll
            for (int it = 0; it < 8; it++) cp16(sdst[it] + so, gsrc[it] + ko);
        }
        cp_commit();
        asm volatile("cp.async.wait_group 3;");
        __syncthreads();

        uint32_t ab = aBase + st * STGSZ, bb = bBase + st * STGSZ;
#pragma unroll
        for (int ks = 0; ks < 4; ks++) {
            uint32_t A[4][4], B[2][4];
#pragma unroll
            for (int mt = 0; mt < 4; mt++)
                ldsm4(A[mt], ab + mt * 2048 + ((aK + ks * 32) ^ sw));
#pragma unroll
            for (int p = 0; p < 2; p++)
                ldsm4(B[p], bb + p * 2048 + ((bK + ks * 32) ^ sw));
#pragma unroll
            for (int mt = 0; mt < 4; mt++)
#pragma unroll
                for (int nt = 0; nt < 4; nt++)
                    mma_tf32(acc[mt][nt], A[mt], B[nt >> 1][(nt & 1) * 2], B[nt >> 1][(nt & 1) * 2 + 1]);
        }
        __syncthreads();
    }

    // ---- epilogue: weighted store to per-slot planes ----
    int g = lane >> 2, t2 = (lane & 3) * 2;
#pragma unroll
    for (int mt = 0; mt < 4; mt++)
#pragma unroll
        for (int nt = 0; nt < 4; nt++) {
            int j = n0 + nw * 32 + nt * 8 + t2;
            int r0 = mw * 64 + mt * 16 + g, r1 = r0 + 8;
            int p0 = s_pair[r0], p1 = s_pair[r1];
            if (p0 >= 0) {
                float wf = g_wt[p0];
                *(float2*)(g_os + (size_t)p0 * HD + j) =
                    make_float2(wf * acc[mt][nt][0], wf * acc[mt][nt][1]);
            }
            if (p1 >= 0) {
                float wf = g_wt[p1];
                *(float2*)(g_os + (size_t)p1 * HD + j) =
                    make_float2(wf * acc[mt][nt][2], wf * acc[mt][nt][3]);
            }
        }
}

// ------------------------- combine ----------------------------------------
__global__ void combine_kernel(float4* __restrict__ out) {
    int i = blockIdx.x * 256 + threadIdx.x;          // over TOK*HD/4
    int t = i >> 8;                                  // 256 float4 per row
    int h4 = i & 255;
    const float4* a = reinterpret_cast<const float4*>(g_os);
    float4 x = a[(size_t)(2 * t) * 256 + h4];
    float4 y = a[(size_t)(2 * t + 1) * 256 + h4];
    out[i] = make_float4(x.x + y.x, x.y + y.y, x.z + y.z, x.w + y.w);
}

// ------------------------- launch -----------------------------------------
extern "C" void kernel_launch(void* const* d_in, const int* in_sizes, int n_in,
                              void* d_out, int out_size) {
    const float* x    = (const float*)d_in[0];
    const float* rl   = (const float*)d_in[1];
    const float* w13  = (const float*)d_in[2];
    const float* w13s = (const float*)d_in[3];
    const float* w2   = (const float*)d_in[4];
    const float* w2s  = (const float*)d_in[5];
    float* out = (float*)d_out;

    const int DSM = NSTG * STGSZ + 1024;   // 132 KB
    cudaFuncSetAttribute(gemm1_kernel, cudaFuncAttributeMaxDynamicSharedMemorySize, DSM);
    cudaFuncSetAttribute(gemm2_kernel, cudaFuncAttributeMaxDynamicSharedMemorySize, DSM);

    float* w13q_p; cudaGetSymbolAddress((void**)&w13q_p, w13q);
    float* w2q_p;  cudaGetSymbolAddress((void**)&w2q_p,  w2q);

    routing_kernel<<<1, TOK>>>(rl);
    convert_x_kernel<<<(TOK * HD) / (256 * 16), 256>>>(x);
    convert_w13_kernel<<<(NE * 2 * ID * HD) / (256 * 16), 256>>>(w13, w13s);
    convert_w2_kernel<<<(NE * HD * ID) / (256 * 16), 256>>>(w2, w2s);

    dim3 g1(ID / 64, 8, NE);    // 12 x 8 x 8 (m-tiles beyond Me early-exit)
    gemm1_kernel<<<g1, 256, DSM>>>(w13q_p);

    dim3 g2(HD / 128, 8, NE);   // 8 x 8 x 8
    gemm2_kernel<<<g2, 256, DSM>>>(w2q_p);

    combine_kernel<<<(TOK * HD) / (4 * 256), 256>>>(reinterpret_cast<float4*>(out));
}